// round 16
// baseline (speedup 1.0000x reference)
#include <cuda_runtime.h>
#include <cstdint>

// Problem constants
#define H_   128
#define W_   256
#define C_   128
#define B_   8
#define HW_  (H_ * W_)
#define CHW_ (C_ * HW_)

// Tiling
#define TH   8              // output rows per block
#define TW   32             // output cols per block
#define NDY  9              // dy values (threadIdx.y)
#define CC   8              // channels per chunk
#define NC   (C_ / CC)      // 16 chunks
#define X2H  (TH + 8)       // 16 x2 rows in tile
#define X2W  52             // 48 data cols + 4 pad (conflict-free, 16B-aligned rows)
#define S1   (CC * TH * TW)          // x1 tile floats  = 2048
#define S2   (CC * X2H * X2W)        // x2 tile floats  = 6656
#define BUFF (S1 + S2)               // 8704 floats per buffer
#define SMEM_BYTES (2 * BUFF * 4)    // 69632 B (double buffered) -> 2 CTAs/SM
#define NTHREADS 288

typedef unsigned long long ull;

__device__ __forceinline__ void fma2(ull& d, ull a, ull b) {
    // packed f32x2 FMA: d.lo += a.lo*b.lo ; d.hi += a.hi*b.hi
    asm("fma.rn.f32x2 %0, %1, %2, %0;" : "+l"(d) : "l"(a), "l"(b));
}
__device__ __forceinline__ void upk2(ull v, float& lo, float& hi) {
    unsigned l, h;
    asm("mov.b64 {%0, %1}, %2;" : "=r"(l), "=r"(h) : "l"(v));
    lo = __uint_as_float(l); hi = __uint_as_float(h);
}
// Build odd pair (p.hi, q.lo) from two aligned pairs. The two unpack movs
// copy-propagate to plain register aliases; only the final pack is real SASS
// (2 MOV) — avoids the 64-bit shift extraction path.
__device__ __forceinline__ ull mkodd(ull p, ull q) {
    ull r;
    asm("{\n\t"
        ".reg .b32 plo, phi, qlo, qhi;\n\t"
        "mov.b64 {plo, phi}, %1;\n\t"
        "mov.b64 {qlo, qhi}, %2;\n\t"
        "mov.b64 %0, {phi, qlo};\n\t"
        "}" : "=l"(r) : "l"(p), "l"(q));
    return r;
}
__device__ __forceinline__ void cp16(unsigned sdst, const float* g, bool valid) {
    int sz = valid ? 16 : 0;   // src-size 0 => zero-fill 16B
    asm volatile("cp.async.cg.shared.global [%0], [%1], 16, %2;"
                 :: "r"(sdst), "l"(g), "r"(sz));
}

__global__ void __launch_bounds__(NTHREADS, 2)
corr_kernel(const float* __restrict__ x1, const float* __restrict__ x2,
            float* __restrict__ out)
{
    extern __shared__ float smem[];

    const int b  = blockIdx.z;
    const int h0 = blockIdx.y * TH;
    const int w0 = blockIdx.x * TW;
    const int wg = threadIdx.x;   // 0..3  : group of 8 pixels along w
    const int dy = threadIdx.y;   // 0..8  : vertical displacement index
    const int hz = threadIdx.z;   // 0..7  : row within tile
    const int tid = wg + 4 * dy + 36 * hz;

    const unsigned smem_u = (unsigned)__cvta_generic_to_shared(smem);

    // ---- loader roles (chunk-invariant) ----
    const bool isX2 = (tid < 192);
    const bool isX1 = (tid >= 192) && (tid < 256);
    int  l_goff = 0, l_soff = 0;
    bool l_valid = false;
    if (isX2) {
        int r  = tid / 12, c4 = tid % 12;
        int gh = h0 - 4 + r;
        int gw = w0 - 8 + c4 * 4;          // tile starts at w0-8 for 16B alignment
        l_valid = (gh >= 0) && (gh < H_) && (gw >= 0) && (gw < W_);
        l_goff  = l_valid ? (b * CHW_ + gh * W_ + gw) : 0;
        l_soff  = r * X2W + c4 * 4;
    } else if (isX1) {
        int t  = tid - 192;
        int r  = t >> 3, c4 = t & 7;
        l_goff = b * CHW_ + (h0 + r) * W_ + w0 + c4 * 4;
        l_soff = r * TW + c4 * 4;
        l_valid = true;
    }

    auto issue = [&](int k, int bsel) {
        if (isX2) {
            const float* g = x2 + (size_t)k * CC * HW_ + l_goff;
            unsigned s = smem_u + (unsigned)((bsel * BUFF + S1 + l_soff) * 4);
            #pragma unroll
            for (int c = 0; c < CC; ++c)
                cp16(s + (unsigned)(c * (X2H * X2W * 4)), g + (size_t)c * HW_, l_valid);
        } else if (isX1) {
            const float* g = x1 + (size_t)k * CC * HW_ + l_goff;
            unsigned s = smem_u + (unsigned)((bsel * BUFF + l_soff) * 4);
            #pragma unroll
            for (int c = 0; c < CC; ++c)
                cp16(s + (unsigned)(c * (TH * TW * 4)), g + (size_t)c * HW_, true);
        }
        asm volatile("cp.async.commit_group;");
    };

    // ---- accumulators: acc[dx*4+p] covers pixels (2p, 2p+1) ----
    ull acc[36];
    #pragma unroll
    for (int i = 0; i < 36; ++i) acc[i] = 0ull;

    issue(0, 0);

    const int arow = hz * TW + wg * 8;
    const int brow = (hz + dy) * X2W + 4 + wg * 8;   // br[j] = x2[w0 - 4 + j]

    #pragma unroll 1
    for (int k = 0; k < NC; ++k) {
        if (k + 1 < NC) issue(k + 1, (k + 1) & 1);
        if (k + 1 < NC) asm volatile("cp.async.wait_group 1;");
        else            asm volatile("cp.async.wait_group 0;");
        __syncthreads();

        const float* s1p = smem + (k & 1) * BUFF;
        const float* s2p = s1p + S1;

        // software pipeline: prefetch B for channel 0
        const float* br0 = s2p + brow;
        ulonglong2 nb01 = *(const ulonglong2*)(br0);
        ulonglong2 nb23 = *(const ulonglong2*)(br0 + 4);
        ulonglong2 nb45 = *(const ulonglong2*)(br0 + 8);
        ulonglong2 nb67 = *(const ulonglong2*)(br0 + 12);

        #pragma unroll
        for (int c = 0; c < CC; ++c) {
            // rotate current B in (register renaming, no SASS cost)
            ulonglong2 b01 = nb01, b23 = nb23, b45 = nb45, b67 = nb67;

            // prefetch next channel's B while we compute this one
            if (c + 1 < CC) {
                const float* brn = s2p + (c + 1) * (X2H * X2W) + brow;
                nb01 = *(const ulonglong2*)(brn);
                nb23 = *(const ulonglong2*)(brn + 4);
                nb45 = *(const ulonglong2*)(brn + 8);
                nb67 = *(const ulonglong2*)(brn + 12);
            }

            // A: 4 aligned pairs (broadcast across dy lanes -> cheap)
            const float* ap = s1p + c * (TH * TW) + arow;
            ulonglong2 av0 = *(const ulonglong2*)(ap);
            ulonglong2 av1 = *(const ulonglong2*)(ap + 4);
            ull A0 = av0.x, A1 = av0.y, A2 = av1.x, A3 = av1.y;

            ull BPe[8] = { b01.x, b01.y, b23.x, b23.y,
                           b45.x, b45.y, b67.x, b67.y };

            // odd-offset pairs: exactly one 2-MOV pack each
            ull BO[7];
            #pragma unroll
            for (int j = 0; j < 7; ++j)
                BO[j] = mkodd(BPe[j], BPe[j + 1]);   // (b[2j+1], b[2j+2])

            // even dx = 2e: B pair offset 2p+dx -> BPe[p + e]
            #pragma unroll
            for (int e = 0; e < 5; ++e) {
                fma2(acc[(2 * e) * 4 + 0], A0, BPe[e + 0]);
                fma2(acc[(2 * e) * 4 + 1], A1, BPe[e + 1]);
                fma2(acc[(2 * e) * 4 + 2], A2, BPe[e + 2]);
                fma2(acc[(2 * e) * 4 + 3], A3, BPe[e + 3]);
            }
            // odd dx = 2o+1: B pair offset 2p+dx -> BO[p + o]
            #pragma unroll
            for (int o = 0; o < 4; ++o) {
                fma2(acc[(2 * o + 1) * 4 + 0], A0, BO[o + 0]);
                fma2(acc[(2 * o + 1) * 4 + 1], A1, BO[o + 1]);
                fma2(acc[(2 * o + 1) * 4 + 2], A2, BO[o + 2]);
                fma2(acc[(2 * o + 1) * 4 + 3], A3, BO[o + 3]);
            }
        }
        __syncthreads();
    }

    // ---- epilogue: mean over C, LeakyReLU(0.1), aligned float4 stores ----
    const float inv = 1.0f / 128.0f;
    const int h  = h0 + hz;
    const int wb = w0 + wg * 8;
    #pragma unroll
    for (int dx = 0; dx < 9; ++dx) {
        const int d = dy * 9 + dx;
        float r[8];
        #pragma unroll
        for (int p = 0; p < 4; ++p) {
            float lo, hi;
            upk2(acc[dx * 4 + p], lo, hi);
            lo *= inv; hi *= inv;
            r[2 * p]     = (lo > 0.0f) ? lo : 0.1f * lo;
            r[2 * p + 1] = (hi > 0.0f) ? hi : 0.1f * hi;
        }
        float4* op = (float4*)(out + (size_t)((b * 81 + d) * H_ + h) * W_ + wb);
        op[0] = make_float4(r[0], r[1], r[2], r[3]);
        op[1] = make_float4(r[4], r[5], r[6], r[7]);
    }
}

extern "C" void kernel_launch(void* const* d_in, const int* in_sizes, int n_in,
                              void* d_out, int out_size)
{
    const float* x1 = (const float*)d_in[0];
    const float* x2 = (const float*)d_in[1];
    float* out = (float*)d_out;

    cudaFuncSetAttribute(corr_kernel,
                         cudaFuncAttributeMaxDynamicSharedMemorySize, SMEM_BYTES);

    dim3 grid(W_ / TW, H_ / TH, B_);   // (8, 16, 8) = 1024 blocks
    dim3 block(4, NDY, TH);            // 288 threads
    corr_kernel<<<grid, block, SMEM_BYTES>>>(x1, x2, out);
}